// round 2
// baseline (speedup 1.0000x reference)
#include <cuda_runtime.h>
#include <math.h>

#define BB 128
#define QQ 500
#define NCLS 80
#define TT 64

// ---------------- Kernel 1: cost matrix ----------------
// grid (32, 128), 256 threads. Each block: one image b, 16 q-rows (2 per warp).
#define K1_THREADS 256
#define QPB 16

__global__ __launch_bounds__(K1_THREADS)
void cost_kernel(const float* __restrict__ logits,   // [B,Q,C]
                 const float* __restrict__ pboxes,   // [B,Q,4]
                 const int*   __restrict__ tids,     // [B,T]
                 const float* __restrict__ tboxes,   // [B,T,4]
                 const float* __restrict__ imgsz,    // [B,4]
                 float*       __restrict__ out)      // [B,Q,T]
{
    __shared__ float s_inv[4];
    __shared__ float s_tn[TT][4];   // normalized targets
    __shared__ float s_tr[TT][4];   // raw targets
    __shared__ float s_ta[TT];      // target areas
    __shared__ int   s_cls[TT];

    const int b   = blockIdx.y;
    const int tid = threadIdx.x;

    if (tid < 4) s_inv[tid] = 1.0f / imgsz[b * 4 + tid];
    __syncthreads();

    if (tid < TT) {
        float4 tb = ((const float4*)tboxes)[b * TT + tid];
        s_tr[tid][0] = tb.x; s_tr[tid][1] = tb.y;
        s_tr[tid][2] = tb.z; s_tr[tid][3] = tb.w;
        s_tn[tid][0] = tb.x * s_inv[0]; s_tn[tid][1] = tb.y * s_inv[1];
        s_tn[tid][2] = tb.z * s_inv[2]; s_tn[tid][3] = tb.w * s_inv[3];
        s_ta[tid] = (tb.z - tb.x) * (tb.w - tb.y);
        s_cls[tid] = tids[b * TT + tid];
    }
    __syncthreads();

    const int lane = tid & 31;
    const int wrp  = tid >> 5;
    const float* lg = logits + (size_t)b * QQ * NCLS;
    float* Cout = out + (size_t)b * QQ * TT;

    const float invx = s_inv[0], invy = s_inv[1], invz = s_inv[2], invw = s_inv[3];

    #pragma unroll
    for (int rep = 0; rep < 2; rep++) {
        int q = blockIdx.x * QPB + wrp * 2 + rep;
        if (q >= QQ) continue;

        float4 pb = ((const float4*)pboxes)[b * QQ + q];  // broadcast across warp
        float bnx = pb.x * invx, bny = pb.y * invy;
        float bnz = pb.z * invz, bnw = pb.w * invw;
        float pa  = (pb.z - pb.x) * (pb.w - pb.y);
        const float* lgq = lg + q * NCLS;
        float* oq = Cout + q * TT;

        #pragma unroll
        for (int rr = 0; rr < 2; rr++) {
            int t = lane + rr * 32;

            // focal class cost
            float x = __ldg(lgq + s_cls[t]);
            float p = 1.0f / (1.0f + expf(-x));
            float omp = 1.0f - p;
            float pos = 0.25f * omp * omp * (-logf(p + 1e-8f));
            float neg = 0.75f * p * p * (-log1pf(-p + 1e-8f));
            float ccost = pos - neg;

            // L1 on normalized boxes
            float l1 = fabsf(bnx - s_tn[t][0]) + fabsf(bny - s_tn[t][1])
                     + fabsf(bnz - s_tn[t][2]) + fabsf(bnw - s_tn[t][3]);

            // GIoU on raw boxes
            float bx1 = s_tr[t][0], by1 = s_tr[t][1];
            float bx2 = s_tr[t][2], by2 = s_tr[t][3];
            float iwd = fmaxf(fminf(pb.z, bx2) - fmaxf(pb.x, bx1), 0.0f);
            float ihd = fmaxf(fminf(pb.w, by2) - fmaxf(pb.y, by1), 0.0f);
            float inter = iwd * ihd;
            float uni = pa + s_ta[t] - inter;
            float iou = inter / uni;
            float ewd = fmaxf(fmaxf(pb.z, bx2) - fminf(pb.x, bx1), 0.0f);
            float ehd = fmaxf(fmaxf(pb.w, by2) - fminf(pb.y, by1), 0.0f);
            float enc = ewd * ehd;
            float giou = iou - (enc - uni) / enc;

            oq[t] = 5.0f * l1 + 2.0f * ccost - 2.0f * giou;
        }
    }
}

// ---------------- Kernel 2: greedy assignment ----------------
#define K2_THREADS 512
#define TPAD 65

__device__ __forceinline__ unsigned int f2ord(float f) {
    unsigned int u = __float_as_uint(f);
    return (u & 0x80000000u) ? ~u : (u | 0x80000000u);
}

__global__ __launch_bounds__(K2_THREADS, 1)
void assign_kernel(const float* __restrict__ C,   // [B,Q,T] (== out base)
                   float*       __restrict__ out)
{
    extern __shared__ float Cm[];                 // QQ * TPAD
    __shared__ unsigned long long partials[16];
    __shared__ unsigned long long winner_sm;
    __shared__ unsigned long long colmask_sm;

    const int b = blockIdx.x;
    const int tid = threadIdx.x;
    const int lane = tid & 31;
    const int wrp  = tid >> 5;

    const float* Cg = C + (size_t)b * QQ * TT;
    // coalesced float4 load of the 500x64 tile into padded smem
    for (int i = tid; i < QQ * TT / 4; i += K2_THREADS) {
        float4 v = ((const float4*)Cg)[i];
        int q = i >> 4;           // 16 float4 per row
        int t = (i & 15) * 4;
        float* r = Cm + q * TPAD + t;
        r[0] = v.x; r[1] = v.y; r[2] = v.z; r[3] = v.w;
    }
    if (tid == 0) colmask_sm = 0ull;
    __syncthreads();

    // thread tid owns row tid: rowmin/rowarg live in registers
    float rmin = INFINITY;
    int   rarg = 0;
    if (tid < QQ) {
        const float* row = Cm + tid * TPAD;
        #pragma unroll 8
        for (int j = 0; j < TT; j++) {
            float v = row[j];
            if (v < rmin) { rmin = v; rarg = j; }
        }
    }

    float* rows_out = out + (size_t)BB * QQ * TT + (size_t)b * TT;
    float* cols_out = rows_out + (size_t)BB * TT;

    for (int s = 0; s < TT; s++) {
        // key = (ordered(value) << 15) | ravel ; ravel asc = exact reference tie-break
        unsigned long long key = 0xFFFFFFFFFFFFFFFFull;
        if (tid < QQ)
            key = ((unsigned long long)f2ord(rmin) << 15)
                | (unsigned int)(tid * TT + rarg);

        #pragma unroll
        for (int off = 16; off; off >>= 1) {
            unsigned long long o = __shfl_down_sync(0xffffffffu, key, off);
            if (o < key) key = o;
        }
        if (lane == 0) partials[wrp] = key;
        __syncthreads();

        if (tid < 16) {
            unsigned long long k2 = partials[tid];
            #pragma unroll
            for (int off = 8; off; off >>= 1) {
                unsigned long long o = __shfl_down_sync(0xffffu, k2, off);
                if (o < k2) k2 = o;
            }
            if (tid == 0) {
                winner_sm = k2;
                colmask_sm |= 1ull << (k2 & 63ull);
            }
        }
        __syncthreads();

        unsigned long long win = winner_sm;
        int ravel = (int)(win & 0x7FFFull);
        int i = ravel >> 6;
        int j = ravel & 63;

        if (tid == 0) {
            rows_out[s] = (float)i;
            cols_out[s] = (float)j;
        }
        if (tid == i) rmin = INFINITY;

        if (s < TT - 1 && tid < QQ && rarg == j && rmin < INFINITY) {
            unsigned long long avail = ~colmask_sm;
            const float* row = Cm + tid * TPAD;
            rmin = INFINITY; rarg = 0;
            #pragma unroll 4
            for (int jj = 0; jj < TT; jj++) {
                if ((avail >> jj) & 1ull) {
                    float v = row[jj];
                    if (v < rmin) { rmin = v; rarg = jj; }
                }
            }
        }
    }
}

extern "C" void kernel_launch(void* const* d_in, const int* in_sizes, int n_in,
                              void* d_out, int out_size) {
    const float* logits = (const float*)d_in[0];   // [128,500,80]
    const float* pboxes = (const float*)d_in[1];   // [128,500,4]
    const int*   tids   = (const int*)  d_in[2];   // [128,64]
    const float* tboxes = (const float*)d_in[3];   // [128,64,4]
    const float* imgsz  = (const float*)d_in[4];   // [128,4]
    float* out = (float*)d_out;

    dim3 g1((QQ + QPB - 1) / QPB, BB);
    cost_kernel<<<g1, K1_THREADS>>>(logits, pboxes, tids, tboxes, imgsz, out);

    const int smem_bytes = QQ * TPAD * (int)sizeof(float);
    cudaFuncSetAttribute(assign_kernel,
                         cudaFuncAttributeMaxDynamicSharedMemorySize, smem_bytes);
    assign_kernel<<<BB, K2_THREADS, smem_bytes>>>(out, out);
}

// round 3
// speedup vs baseline: 1.8518x; 1.8518x over previous
#include <cuda_runtime.h>
#include <math.h>

#define BB 128
#define QQ 500
#define NCLS 80
#define TT 64
#define NT 512
#define CSTR 513   // column stride in floats (rows padded: 513 % 32 == 1, conflict-free both ways)

// smem byte offsets (Cm column-major: Cm[j*CSTR + q])
#define OFF_CM    0
#define OFF_KEY   131328                  // 64*513*4
#define OFF_PR    131840                  // +64*8
#define OFF_BN    139840                  // +500*16
#define OFF_TR    147840                  // +500*16
#define OFF_TN    148864                  // +64*16
#define OFF_PA    149888                  // +64*16
#define OFF_TA    151888                  // +500*4
#define OFF_CLS   152144                  // +64*4
#define SMEM_SZ   152400                  // +64*4

__device__ __forceinline__ unsigned int f2ord(float f) {
    unsigned int u = __float_as_uint(f);
    return (u & 0x80000000u) ? ~u : (u | 0x80000000u);
}
__device__ __forceinline__ unsigned long long umin64(unsigned long long a,
                                                     unsigned long long b) {
    return a < b ? a : b;
}

// warp-cooperative exact (value, ravel) min over one column; all lanes return the min
__device__ __forceinline__ unsigned long long colscan(const float* __restrict__ Cm,
                                                      int col, int lane) {
    unsigned long long best = ~0ull;
    const float* p = Cm + col * CSTR;
    #pragma unroll
    for (int it = 0; it < 16; it++) {
        int q = lane + it * 32;
        if (q < QQ) {
            unsigned long long k =
                ((unsigned long long)f2ord(p[q]) << 15) | (unsigned)(q * TT + col);
            best = umin64(best, k);
        }
    }
    #pragma unroll
    for (int off = 16; off; off >>= 1)
        best = umin64(best, __shfl_xor_sync(0xffffffffu, best, off));
    return best;
}

__global__ __launch_bounds__(NT, 1)
void hungarian_fused(const float* __restrict__ logits,   // [B,Q,C]
                     const float* __restrict__ pboxes,   // [B,Q,4]
                     const int*   __restrict__ tids,     // [B,T]
                     const float* __restrict__ tboxes,   // [B,T,4]
                     const float* __restrict__ imgsz,    // [B,4]
                     float*       __restrict__ out)
{
    extern __shared__ char smraw[];
    float*  Cm    = (float*) (smraw + OFF_CM);
    unsigned long long* s_key = (unsigned long long*)(smraw + OFF_KEY);
    float4* s_pr  = (float4*)(smraw + OFF_PR);
    float4* s_bn  = (float4*)(smraw + OFF_BN);
    float4* s_tr  = (float4*)(smraw + OFF_TR);
    float4* s_tn  = (float4*)(smraw + OFF_TN);
    float*  s_pa  = (float*) (smraw + OFF_PA);
    float*  s_ta  = (float*) (smraw + OFF_TA);
    int*    s_cls = (int*)   (smraw + OFF_CLS);

    const int b = blockIdx.x, tid = threadIdx.x;
    const int lane = tid & 31, wrp = tid >> 5;

    const float inv0 = 1.0f / imgsz[b * 4 + 0];
    const float inv1 = 1.0f / imgsz[b * 4 + 1];
    const float inv2 = 1.0f / imgsz[b * 4 + 2];
    const float inv3 = 1.0f / imgsz[b * 4 + 3];

    if (tid < TT) {
        float4 tb = ((const float4*)tboxes)[b * TT + tid];
        s_tr[tid] = tb;
        s_tn[tid] = make_float4(tb.x * inv0, tb.y * inv1, tb.z * inv2, tb.w * inv3);
        s_ta[tid] = (tb.z - tb.x) * (tb.w - tb.y);
        s_cls[tid] = tids[b * TT + tid];
    }
    if (tid < QQ) {
        float4 pb = ((const float4*)pboxes)[b * QQ + tid];
        s_pr[tid] = pb;
        s_bn[tid] = make_float4(pb.x * inv0, pb.y * inv1, pb.z * inv2, pb.w * inv3);
        s_pa[tid] = (pb.z - pb.x) * (pb.w - pb.y);
    }
    __syncthreads();

    // ---- Phase 1: cost matrix (per-thread target data is loop-invariant) ----
    const int t = tid & 63;
    const float4 tr = s_tr[t];
    const float4 tn = s_tn[t];
    const float  ta = s_ta[t];
    const int    cl = s_cls[t];
    const float* lg = logits + (size_t)b * QQ * NCLS;
    float* Cout = out + (size_t)b * QQ * TT;

    for (int idx = tid; idx < QQ * TT; idx += NT) {
        int q = idx >> 6;
        float4 pb = s_pr[q];
        float4 bn = s_bn[q];
        float  pa = s_pa[q];

        float x = __ldg(lg + q * NCLS + cl);
        float p = 1.0f / (1.0f + expf(-x));
        float omp = 1.0f - p;
        float pos = 0.25f * omp * omp * (-logf(p + 1e-8f));
        float neg = 0.75f * p * p * (-log1pf(-p + 1e-8f));
        float ccost = pos - neg;

        float l1 = fabsf(bn.x - tn.x) + fabsf(bn.y - tn.y)
                 + fabsf(bn.z - tn.z) + fabsf(bn.w - tn.w);

        float iwd = fmaxf(fminf(pb.z, tr.z) - fmaxf(pb.x, tr.x), 0.0f);
        float ihd = fmaxf(fminf(pb.w, tr.w) - fmaxf(pb.y, tr.y), 0.0f);
        float inter = iwd * ihd;
        float uni = pa + ta - inter;
        float iou = inter / uni;
        float ewd = fmaxf(fmaxf(pb.z, tr.z) - fminf(pb.x, tr.x), 0.0f);
        float ehd = fmaxf(fmaxf(pb.w, tr.w) - fminf(pb.y, tr.y), 0.0f);
        float enc = ewd * ehd;
        float giou = iou - (enc - uni) / enc;

        float cost = 5.0f * l1 + 2.0f * ccost - 2.0f * giou;
        Cm[t * CSTR + q] = cost;   // column-major, conflict-free (stride 513)
        Cout[idx] = cost;          // coalesced
    }
    __syncthreads();

    // ---- Phase 2: initial per-column min keys (16 warps, 4 cols each) ----
    for (int j = wrp; j < TT; j += 16) {
        unsigned long long best = colscan(Cm, j, lane);
        if (lane == 0) s_key[j] = best;
    }
    __syncthreads();

    if (wrp != 0) return;   // greedy loop runs entirely in warp 0

    // ---- Phase 3: greedy assignment, column keys in registers (2/lane) ----
    unsigned long long k0 = s_key[lane];
    unsigned long long k1 = s_key[lane + 32];
    const unsigned long long KMAX = ~0ull;
    const float FINF = __int_as_float(0x7F800000);

    float* rows_out = out + (size_t)BB * QQ * TT + (size_t)b * TT;
    float* cols_out = rows_out + (size_t)BB * TT;

    for (int s = 0; s < TT; s++) {
        unsigned long long m = umin64(k0, k1);
        #pragma unroll
        for (int off = 16; off; off >>= 1)
            m = umin64(m, __shfl_xor_sync(0xffffffffu, m, off));

        int ravel = (int)(m & 0x7FFFull);
        int i = ravel >> 6;
        int j = ravel & 63;
        if (lane == 0) { rows_out[s] = (float)i; cols_out[s] = (float)j; }
        if (s == TT - 1) break;

        // consume column j
        if (j < 32) { if (lane == j) k0 = KMAX; }
        else        { if (lane == j - 32) k1 = KMAX; }

        // consume row i: poison it in every column (no masking needed later)
        Cm[lane * CSTR + i] = FINF;
        Cm[(lane + 32) * CSTR + i] = FINF;
        __syncwarp();

        // rescan only columns whose cached argmin row was just consumed (rare)
        bool n0 = (k0 != KMAX) && ((int)((k0 >> 6) & 0x1FFull) == i);
        bool n1 = (k1 != KMAX) && ((int)((k1 >> 6) & 0x1FFull) == i);
        unsigned bal0 = __ballot_sync(0xffffffffu, n0);
        unsigned bal1 = __ballot_sync(0xffffffffu, n1);
        while (bal0) {
            int c = __ffs(bal0) - 1; bal0 &= bal0 - 1;
            unsigned long long nk = colscan(Cm, c, lane);
            if (lane == c) k0 = nk;
        }
        while (bal1) {
            int c = __ffs(bal1) - 1; bal1 &= bal1 - 1;
            unsigned long long nk = colscan(Cm, c + 32, lane);
            if (lane == c) k1 = nk;
        }
    }
}

extern "C" void kernel_launch(void* const* d_in, const int* in_sizes, int n_in,
                              void* d_out, int out_size) {
    const float* logits = (const float*)d_in[0];   // [128,500,80]
    const float* pboxes = (const float*)d_in[1];   // [128,500,4]
    const int*   tids   = (const int*)  d_in[2];   // [128,64]
    const float* tboxes = (const float*)d_in[3];   // [128,64,4]
    const float* imgsz  = (const float*)d_in[4];   // [128,4]
    float* out = (float*)d_out;

    cudaFuncSetAttribute(hungarian_fused,
                         cudaFuncAttributeMaxDynamicSharedMemorySize, SMEM_SZ);
    hungarian_fused<<<BB, NT, SMEM_SZ>>>(logits, pboxes, tids, tboxes, imgsz, out);
}

// round 5
// speedup vs baseline: 3.8830x; 2.0969x over previous
#include <cuda_runtime.h>
#include <math.h>

#define BB 128
#define QQ 500
#define NCLS 80
#define TT 64
#define FULL 0xffffffffu

// ================= Kernel A: cost matrix (high occupancy) =================
// grid (16, 128), 256 threads; block handles 32 q-rows of one image.
#define KA_THREADS 256

__global__ __launch_bounds__(KA_THREADS)
void cost_kernel(const float* __restrict__ logits,   // [B,Q,C]
                 const float* __restrict__ pboxes,   // [B,Q,4]
                 const int*   __restrict__ tids,     // [B,T]
                 const float* __restrict__ tboxes,   // [B,T,4]
                 const float* __restrict__ imgsz,    // [B,4]
                 float*       __restrict__ out)      // [B,Q,T]
{
    __shared__ float4 s_tr[TT];
    __shared__ float4 s_tn[TT];
    __shared__ float  s_ta[TT];
    __shared__ int    s_cls[TT];

    const int b   = blockIdx.y;
    const int tid = threadIdx.x;

    const float inv0 = 1.0f / imgsz[b * 4 + 0];
    const float inv1 = 1.0f / imgsz[b * 4 + 1];
    const float inv2 = 1.0f / imgsz[b * 4 + 2];
    const float inv3 = 1.0f / imgsz[b * 4 + 3];

    if (tid < TT) {
        float4 tb = ((const float4*)tboxes)[b * TT + tid];
        s_tr[tid] = tb;
        s_tn[tid] = make_float4(tb.x * inv0, tb.y * inv1, tb.z * inv2, tb.w * inv3);
        s_ta[tid] = (tb.z - tb.x) * (tb.w - tb.y);
        s_cls[tid] = tids[b * TT + tid];
    }
    __syncthreads();

    const int t = tid & 63;
    const float4 tr = s_tr[t];
    const float4 tn = s_tn[t];
    const float  ta = s_ta[t];
    const int    cl = s_cls[t];

    const float* lg   = logits + (size_t)b * QQ * NCLS;
    float*       Cout = out    + (size_t)b * QQ * TT;

    #pragma unroll
    for (int rep = 0; rep < 8; rep++) {
        int q = blockIdx.x * 32 + rep * 4 + (tid >> 6);
        if (q >= QQ) break;

        float4 pb = ((const float4*)pboxes)[b * QQ + q];
        float bnx = pb.x * inv0, bny = pb.y * inv1;
        float bnz = pb.z * inv2, bnw = pb.w * inv3;
        float pa  = (pb.z - pb.x) * (pb.w - pb.y);

        float x = __ldg(lg + q * NCLS + cl);
        float p = 1.0f / (1.0f + expf(-x));
        float omp = 1.0f - p;
        float pos = 0.25f * omp * omp * (-logf(p + 1e-8f));
        float neg = 0.75f * p * p * (-log1pf(-p + 1e-8f));
        float ccost = pos - neg;

        float l1 = fabsf(bnx - tn.x) + fabsf(bny - tn.y)
                 + fabsf(bnz - tn.z) + fabsf(bnw - tn.w);

        float iwd = fmaxf(fminf(pb.z, tr.z) - fmaxf(pb.x, tr.x), 0.0f);
        float ihd = fmaxf(fminf(pb.w, tr.w) - fmaxf(pb.y, tr.y), 0.0f);
        float inter = iwd * ihd;
        float uni = pa + ta - inter;
        float iou = inter / uni;
        float ewd = fmaxf(fmaxf(pb.z, tr.z) - fminf(pb.x, tr.x), 0.0f);
        float ehd = fmaxf(fmaxf(pb.w, tr.w) - fminf(pb.y, tr.y), 0.0f);
        float enc = ewd * ehd;
        float giou = iou - (enc - uni) / enc;

        Cout[q * TT + t] = 5.0f * l1 + 2.0f * ccost - 2.0f * giou;
    }
}

// ================= Kernel B: greedy assignment =================
#define KB_THREADS 512
#define CSTR 513   // column-major stride: bank = (j+q)%32 -> conflict-free column scans

#define OFF_CM   0
#define OFF_VAL  (TT * CSTR * 4)          // 131328
#define OFF_ROW  (OFF_VAL + TT * 4)
#define KB_SMEM  (OFF_ROW + TT * 4)

__device__ __forceinline__ unsigned int f2ord(float f) {
    unsigned int u = __float_as_uint(f);
    return (u & 0x80000000u) ? ~u : (u | 0x80000000u);
}

// warp-cooperative exact (value, smallest-row) min over one column
__device__ __forceinline__ void colscan(const float* __restrict__ Cm, int col,
                                        int lane, unsigned& mv, unsigned& mq) {
    const float* p = Cm + col * CSTR;
    unsigned best = 0xFFFFFFFFu, bq = 0;
    #pragma unroll
    for (int it = 0; it < 16; it++) {
        int q = lane + it * 32;
        if (q < QQ) {
            unsigned u = f2ord(p[q]);
            if (u < best) { best = u; bq = (unsigned)q; }   // ascending q keeps min q on tie
        }
    }
    mv = __reduce_min_sync(FULL, best);
    unsigned r = (best == mv) ? bq : 0xFFFFFFFFu;
    mq = __reduce_min_sync(FULL, r);
}

__global__ __launch_bounds__(KB_THREADS, 1)
void assign_kernel(const float* __restrict__ C,    // [B,Q,T]
                   float*       __restrict__ out)
{
    extern __shared__ char smraw[];
    float*    Cm    = (float*)   (smraw + OFF_CM);
    unsigned* s_val = (unsigned*)(smraw + OFF_VAL);
    unsigned* s_row = (unsigned*)(smraw + OFF_ROW);

    const int b = blockIdx.x, tid = threadIdx.x;
    const int lane = tid & 31, wrp = tid >> 5;

    // load [Q,T] tile, transpose to column-major padded smem
    const float* Cg = C + (size_t)b * QQ * TT;
    for (int i = tid; i < QQ * TT / 4; i += KB_THREADS) {
        float4 v = ((const float4*)Cg)[i];
        int q = i >> 4;
        int j = (i & 15) * 4;
        Cm[(j + 0) * CSTR + q] = v.x;
        Cm[(j + 1) * CSTR + q] = v.y;
        Cm[(j + 2) * CSTR + q] = v.z;
        Cm[(j + 3) * CSTR + q] = v.w;
    }
    __syncthreads();

    // initial per-column (value,row) keys
    for (int j = wrp; j < TT; j += 16) {
        unsigned mv, mq;
        colscan(Cm, j, lane, mv, mq);
        if (lane == 0) { s_val[j] = mv; s_row[j] = mq; }
    }
    __syncthreads();

    if (wrp != 0) return;   // greedy: warp 0 only

    unsigned v0 = s_val[lane],      q0 = s_row[lane];        // col = lane
    unsigned v1 = s_val[lane + 32], q1 = s_row[lane + 32];   // col = lane+32
    const unsigned DEAD = 0xFFFFFFFFu;
    const float FINF = __int_as_float(0x7F800000);

    float* rows_out = out + (size_t)BB * QQ * TT + (size_t)b * TT;
    float* cols_out = rows_out + (size_t)BB * TT;

    #pragma unroll 1
    for (int s = 0; s < TT; s++) {
        unsigned m = __reduce_min_sync(FULL, v0 < v1 ? v0 : v1);
        unsigned r = 0xFFFFFFFFu;
        if (v0 == m) r = (q0 << 6) | (unsigned)lane;
        if (v1 == m) { unsigned r1 = (q1 << 6) | (unsigned)(lane + 32); if (r1 < r) r = r1; }
        r = __reduce_min_sync(FULL, r);   // exact (value, ravel) tie-break

        int i = (int)(r >> 6);
        int j = (int)(r & 63u);
        if (lane == 0) { rows_out[s] = (float)i; cols_out[s] = (float)j; }
        if (s == TT - 1) break;

        // kill column j
        if (lane == (j & 31)) { if (j < 32) v0 = DEAD; else v1 = DEAD; }

        // which live columns cached row i?
        bool n0 = (v0 != DEAD) && (q0 == (unsigned)i);
        bool n1 = (v1 != DEAD) && (q1 == (unsigned)i);

        // poison row i in every column
        Cm[lane * CSTR + i] = FINF;
        Cm[(lane + 32) * CSTR + i] = FINF;

        unsigned bal0 = __ballot_sync(FULL, n0);
        unsigned bal1 = __ballot_sync(FULL, n1);
        if (bal0 | bal1) {
            __syncwarp();   // poisons visible before rescans
            while (bal0) {
                int c = __ffs(bal0) - 1; bal0 &= bal0 - 1;
                unsigned mv, mq;
                colscan(Cm, c, lane, mv, mq);
                if (lane == c) { v0 = mv; q0 = mq; }
            }
            while (bal1) {
                int c = __ffs(bal1) - 1; bal1 &= bal1 - 1;
                unsigned mv, mq;
                colscan(Cm, c + 32, lane, mv, mq);
                if (lane == c) { v1 = mv; q1 = mq; }
            }
        }
    }
}

extern "C" void kernel_launch(void* const* d_in, const int* in_sizes, int n_in,
                              void* d_out, int out_size) {
    const float* logits = (const float*)d_in[0];   // [128,500,80]
    const float* pboxes = (const float*)d_in[1];   // [128,500,4]
    const int*   tids   = (const int*)  d_in[2];   // [128,64]
    const float* tboxes = (const float*)d_in[3];   // [128,64,4]
    const float* imgsz  = (const float*)d_in[4];   // [128,4]
    float* out = (float*)d_out;

    dim3 gA((QQ + 31) / 32, BB);
    cost_kernel<<<gA, KA_THREADS>>>(logits, pboxes, tids, tboxes, imgsz, out);

    cudaFuncSetAttribute(assign_kernel,
                         cudaFuncAttributeMaxDynamicSharedMemorySize, KB_SMEM);
    assign_kernel<<<BB, KB_THREADS, KB_SMEM>>>(out, out);
}